// round 9
// baseline (speedup 1.0000x reference)
#include <cuda_runtime.h>
#include <cuda_fp16.h>
#include <cstdint>
#include <cstddef>

// ---------------------------------------------------------------------------
// Problem constants
// ---------------------------------------------------------------------------
static constexpr int D_DIM  = 2496;   // 16*13*12
static constexpr int B_ROWS = 4096;
static constexpr int S_ROWS = 2048;

// Centered formulation: x~ = x - 0.5, m~ = m - 0.5 (sq_dist shift-invariant).
// out = -0.002*|x~|^2 - 0.002*|m~|^2 + 0.004*(x~.m~)
static constexpr float K_CROSS = 0.004f;
static constexpr float K_SQ    = -0.002f;

// K split: tensor path 70 x 32 = 2240 cols; SIMT HFMA2 path 256 cols (32 x 8).
static constexpr int BM = 64;
static constexpr int BN = 128;
static constexpr int BK = 32;
static constexpr int KITERS_T   = 70;      // tensor iterations
static constexpr int K_TENSOR   = KITERS_T * BK;   // 2240
static constexpr int FMA_CHUNKS = 32;      // 32 chunks x 8 cols = 256
static constexpr int STAGES = 4;
static constexpr int NTHREADS = 256;

// Tensor stage smem: padded rows 64B data + 16B pad.
static constexpr int ROW_STRIDE  = 80;
static constexpr int A_ST_BYTES  = BM * ROW_STRIDE;           // 5120
static constexpr int B_ST_BYTES  = BN * ROW_STRIDE;           // 10240
static constexpr int STAGE_BYTES = A_ST_BYTES + B_ST_BYTES;   // 15360
// FMA chunk buffers: A 64x16B + B 128x16B (B bit-swizzled), ring of 4.
static constexpr int FMA_ST      = 3072;
static constexpr int OFF_FMA     = STAGES * STAGE_BYTES;              // 61440
static constexpr int OFF_STATS   = OFF_FMA + STAGES * FMA_ST;         // 73728
static constexpr int SMEM_BYTES  = OFF_STATS + (BM + BN) * 4;         // 74496
// Merge buffer (post-loop, reuses stage area): 64 rows x 256 B = 16 KB.

// ---------------------------------------------------------------------------
// Device scratch
// ---------------------------------------------------------------------------
__device__ __align__(128) __half g_Xh[(size_t)B_ROWS * D_DIM];
__device__ __align__(128) __half g_Mh[(size_t)S_ROWS * D_DIM];
__device__ float g_ax[B_ROWS];
__device__ float g_bx[S_ROWS];

// ---------------------------------------------------------------------------
// Helpers
// ---------------------------------------------------------------------------
__device__ __forceinline__ uint32_t smem_u32(const void* p) {
    uint32_t a;
    asm("{ .reg .u64 t; cvta.to.shared.u64 t, %1; cvt.u32.u64 %0, t; }"
        : "=r"(a) : "l"(p));
    return a;
}

__device__ __forceinline__ void cp_async16(uint32_t dst, const void* src) {
    asm volatile("cp.async.cg.shared.global [%0], [%1], 16;" :: "r"(dst), "l"(src));
}

__device__ __forceinline__ void ldmat_x4(uint32_t* r, uint32_t addr) {
    asm volatile("ldmatrix.sync.aligned.m8n8.x4.shared.b16 {%0,%1,%2,%3}, [%4];"
                 : "=r"(r[0]), "=r"(r[1]), "=r"(r[2]), "=r"(r[3]) : "r"(addr));
}

__device__ __forceinline__ void mma_f16acc(uint32_t* c, const uint32_t* a,
                                           const uint32_t* b) {
    asm volatile(
        "mma.sync.aligned.m16n8k16.row.col.f16.f16.f16.f16 "
        "{%0,%1}, {%2,%3,%4,%5}, {%6,%7}, {%0,%1};"
        : "+r"(c[0]), "+r"(c[1])
        : "r"(a[0]), "r"(a[1]), "r"(a[2]), "r"(a[3]), "r"(b[0]), "r"(b[1]));
}

// ---------------------------------------------------------------------------
// Tensor stage loader (A 64x32, B 128x32 fp16)
// ---------------------------------------------------------------------------
__device__ __forceinline__ void load_stage(uint32_t sbase,
                                           const __half* __restrict__ Xt,
                                           const __half* __restrict__ Mt,
                                           int tid) {
    {
        int row = tid >> 2, ch = tid & 3;
        cp_async16(sbase + row * ROW_STRIDE + ch * 16,
                   Xt + (size_t)row * D_DIM + ch * 8);
    }
#pragma unroll
    for (int i = 0; i < 2; i++) {
        int idx = i * NTHREADS + tid;
        int row = idx >> 2, ch = idx & 3;
        cp_async16(sbase + A_ST_BYTES + row * ROW_STRIDE + ch * 16,
                   Mt + (size_t)row * D_DIM + ch * 8);
    }
}

// FMA chunk loader: chunk c covers cols [K_TENSOR + c*8, +8).
// A rows linear (stride 16B); B rows bit-swizzled: slot((j<<4)|cg) for n=8cg+j.
__device__ __forceinline__ void load_fma_chunk(uint32_t fbase,
                                               const __half* __restrict__ Xf,
                                               const __half* __restrict__ Mf,
                                               int c, int tid) {
    if (tid < 64) {
        cp_async16(fbase + tid * 16, Xf + (size_t)tid * D_DIM + c * 8);
    } else if (tid < 192) {
        int n = tid - 64;
        uint32_t slot = (uint32_t)(((n & 7) << 4) | (n >> 3));
        cp_async16(fbase + 1024 + slot * 16, Mf + (size_t)n * D_DIM + c * 8);
    }
}

// ---------------------------------------------------------------------------
// Convert: fp32 -> centered fp16, plus prescaled exact row sum-of-squares.
// ---------------------------------------------------------------------------
static constexpr int ROW_F4 = D_DIM / 4;  // 624

__global__ void __launch_bounds__(256)
convert_all_kernel(const float* __restrict__ X, const float* __restrict__ M) {
    const int b = blockIdx.x;
    const bool isX = (b < B_ROWS);
    const int row  = isX ? b : b - B_ROWS;
    const float4* src = (const float4*)((isX ? X : M) + (size_t)row * D_DIM);
    uint2* dst = (uint2*)((isX ? g_Xh : g_Mh) + (size_t)row * D_DIM);
    float* coef = isX ? &g_ax[row] : &g_bx[row];

    float acc = 0.f;
#pragma unroll 3
    for (int i = threadIdx.x; i < ROW_F4; i += 256) {
        float4 v = src[i];
        float c0 = v.x - 0.5f, c1 = v.y - 0.5f;
        float c2 = v.z - 0.5f, c3 = v.w - 0.5f;
        acc = fmaf(c0, c0, acc);
        acc = fmaf(c1, c1, acc);
        acc = fmaf(c2, c2, acc);
        acc = fmaf(c3, c3, acc);
        __half2 lo = __floats2half2_rn(c0, c1);
        __half2 hi = __floats2half2_rn(c2, c3);
        uint2 o;
        o.x = *(uint32_t*)&lo;
        o.y = *(uint32_t*)&hi;
        dst[i] = o;
    }
#pragma unroll
    for (int o = 16; o > 0; o >>= 1) acc += __shfl_xor_sync(0xffffffffu, acc, o);
    __shared__ float wsum[8];
    if ((threadIdx.x & 31) == 0) wsum[threadIdx.x >> 5] = acc;
    __syncthreads();
    if (threadIdx.x == 0) {
        float t = 0.f;
#pragma unroll
        for (int i = 0; i < 8; i++) t += wsum[i];
        *coef = t * K_SQ;
    }
}

// ---------------------------------------------------------------------------
// Hybrid GEMM + fused epilogue: out[b,s] = ax[b] + bx[s] + 0.004 * cross
// Tensor: 8 warps 2(M)x4(N), warp tile 32x32, K=2240.
// SIMT:   256 threads 16x16 groups, thread tile 4Mx8N, K=256 via HFMA2.
// ---------------------------------------------------------------------------
__global__ void __launch_bounds__(NTHREADS, 2)
gemm_kernel(float* __restrict__ out) {
    extern __shared__ char smem[];
    const uint32_t smem_base = smem_u32(smem);
    const int tid    = threadIdx.x;
    const int wid    = tid >> 5;
    const int lane   = tid & 31;
    const int warp_m = wid >> 2;
    const int warp_n = wid & 3;
    const int bn     = blockIdx.x;        // 0..15
    const int bm     = blockIdx.y;        // 0..63
    const int rg     = tid >> 4;          // FMA row group 0..15 (4 rows each)
    const int cg     = tid & 15;          // FMA col group 0..15 (8 cols each)

    float* xs_s = (float*)(smem + OFF_STATS);
    float* ms_s = xs_s + BM;
    if (tid < BM) xs_s[tid] = g_ax[bm * BM + tid];
    if (tid < BN) ms_s[tid] = g_bx[bn * BN + tid];

    const __half* Xbase = g_Xh + (size_t)(bm * BM) * D_DIM;
    const __half* Mbase = g_Mh + (size_t)(bn * BN) * D_DIM;
    const __half* Xf = Xbase + K_TENSOR;
    const __half* Mf = Mbase + K_TENSOR;

    // Prologue: stages 0..2; FMA chunks 0,1 ride along with stages 0,1.
#pragma unroll
    for (int s = 0; s < STAGES - 1; s++) {
        load_stage(smem_base + s * STAGE_BYTES,
                   Xbase + (size_t)s * BK, Mbase + (size_t)s * BK, tid);
        if (s < 2)
            load_fma_chunk(smem_base + OFF_FMA + s * FMA_ST, Xf, Mf, s, tid);
        asm volatile("cp.async.commit_group;" ::: "memory");
    }

    uint32_t acc[2][4][2];
#pragma unroll
    for (int t = 0; t < 2; t++)
#pragma unroll
        for (int u = 0; u < 4; u++) { acc[t][u][0] = 0u; acc[t][u][1] = 0u; }

    __half2 facc[4][4];
#pragma unroll
    for (int r = 0; r < 4; r++)
#pragma unroll
        for (int np = 0; np < 4; np++) facc[r][np] = __half2half2(__ushort_as_half(0));

    const int a_row = warp_m * 32 + (lane & 15);
    const int a_sel = (lane >> 4) * 16;
    const int b_grp = lane >> 3;
    const int b_row = warp_n * 32 + ((b_grp >> 1) * 8) + (lane & 7);
    const int b_sel = (b_grp & 1) * 16;

#pragma unroll 1
    for (int kk = 0; kk < KITERS_T; kk++) {
        asm volatile("cp.async.wait_group 2;" ::: "memory");
        __syncthreads();

        int kn = kk + STAGES - 1;
        if (kn < KITERS_T) {
            load_stage(smem_base + (kn & 3) * STAGE_BYTES,
                       Xbase + (size_t)kn * BK, Mbase + (size_t)kn * BK, tid);
        }
        if (kk & 1) {                           // odd iters: prefetch FMA chunk
            int c = (kk + 3) >> 1;
            if (c < FMA_CHUNKS)
                load_fma_chunk(smem_base + OFF_FMA + (c & 3) * FMA_ST, Xf, Mf, c, tid);
        }
        asm volatile("cp.async.commit_group;" ::: "memory");

        const uint32_t sA = smem_base + (kk & 3) * STAGE_BYTES;
        const uint32_t sB = sA + A_ST_BYTES;

#pragma unroll
        for (int ks = 0; ks < 2; ks++) {
            const int koff = ks * 32;
            uint32_t a[2][4], b[4][2];
#pragma unroll
            for (int t = 0; t < 2; t++)
                ldmat_x4(a[t], sA + (a_row + t * 16) * ROW_STRIDE + koff + a_sel);
#pragma unroll
            for (int v = 0; v < 2; v++) {
                uint32_t r[4];
                ldmat_x4(r, sB + (b_row + v * 16) * ROW_STRIDE + koff + b_sel);
                b[v * 2 + 0][0] = r[0]; b[v * 2 + 0][1] = r[1];
                b[v * 2 + 1][0] = r[2]; b[v * 2 + 1][1] = r[3];
            }
#pragma unroll
            for (int t = 0; t < 2; t++)
#pragma unroll
                for (int u = 0; u < 4; u++)
                    mma_f16acc(acc[t][u], a[t], b[u]);
        }

        // SIMT HFMA2 path: even iters process chunk kk/2 (ready by pipeline).
        if (((kk & 1) == 0) && ((kk >> 1) < FMA_CHUNKS)) {
            const uint32_t fA = smem_base + OFF_FMA + ((kk >> 1) & 3) * FMA_ST;
            const uint32_t fB = fA + 1024;
#pragma unroll
            for (int kh = 0; kh < 2; kh++) {
                uint32_t ar[4][2], br[8][2];
#pragma unroll
                for (int r = 0; r < 4; r++)
                    asm volatile("ld.shared.v2.u32 {%0,%1}, [%2];"
                        : "=r"(ar[r][0]), "=r"(ar[r][1])
                        : "r"(fA + (rg * 4 + r) * 16 + kh * 8));
#pragma unroll
                for (int j = 0; j < 8; j++)
                    asm volatile("ld.shared.v2.u32 {%0,%1}, [%2];"
                        : "=r"(br[j][0]), "=r"(br[j][1])
                        : "r"(fB + (((j << 4) | cg) * 16) + kh * 8));
#pragma unroll
                for (int k = 0; k < 4; k++) {
                    __half2 b2[4];
#pragma unroll
                    for (int np = 0; np < 4; np++) {
                        __half lo = ((const __half*)br[2 * np])[k];
                        __half hi = ((const __half*)br[2 * np + 1])[k];
                        b2[np] = __halves2half2(lo, hi);
                    }
#pragma unroll
                    for (int r = 0; r < 4; r++) {
                        __half2 a2 = __half2half2(((const __half*)ar[r])[k]);
#pragma unroll
                        for (int np = 0; np < 4; np++)
                            facc[r][np] = __hfma2(a2, b2[np], facc[r][np]);
                    }
                }
            }
        }
    }

    // ---------------- Merge FMA partials through smem ----------------
    __syncthreads();   // all smem reads of the mainloop complete
#pragma unroll
    for (int r = 0; r < 4; r++)
#pragma unroll
        for (int np = 0; np < 4; np++) {
            uint32_t addr = smem_base + (rg * 4 + r) * 256 + (cg * 8 + np * 2) * 2;
            asm volatile("st.shared.u32 [%0], %1;"
                         :: "r"(addr), "r"(*(uint32_t*)&facc[r][np]));
        }
    __syncthreads();

    // ---------------- Epilogue ----------------
    const int g  = lane >> 2;
    const int tg = lane & 3;

#pragma unroll
    for (int t = 0; t < 2; t++) {
        const int r0 = warp_m * 32 + t * 16 + g;
        const float axa = xs_s[r0];
        const float axb = xs_s[r0 + 8];
        float* o0 = out + (size_t)(bm * BM + r0) * S_ROWS + bn * BN;
        float* o1 = o0 + (size_t)8 * S_ROWS;
#pragma unroll
        for (int u = 0; u < 4; u++) {
            const int col = warp_n * 32 + u * 8 + tg * 2;
            const float m0 = ms_s[col], m1 = ms_s[col + 1];
            uint32_t f0u, f1u;
            asm volatile("ld.shared.u32 %0, [%1];"
                         : "=r"(f0u) : "r"(smem_base + r0 * 256 + col * 2));
            asm volatile("ld.shared.u32 %0, [%1];"
                         : "=r"(f1u) : "r"(smem_base + (r0 + 8) * 256 + col * 2));
            float2 cf0 = __half22float2(*(__half2*)&f0u);
            float2 cf1 = __half22float2(*(__half2*)&f1u);
            float2 clo = __half22float2(*(__half2*)&acc[t][u][0]);
            float2 chi = __half22float2(*(__half2*)&acc[t][u][1]);
            float2 v0, v1;
            v0.x = axa + m0 + K_CROSS * (clo.x + cf0.x);
            v0.y = axa + m1 + K_CROSS * (clo.y + cf0.y);
            v1.x = axb + m0 + K_CROSS * (chi.x + cf1.x);
            v1.y = axb + m1 + K_CROSS * (chi.y + cf1.y);
            *(float2*)(o0 + col) = v0;
            *(float2*)(o1 + col) = v1;
        }
    }
}

// ---------------------------------------------------------------------------
// Launch
// ---------------------------------------------------------------------------
extern "C" void kernel_launch(void* const* d_in, const int* in_sizes, int n_in,
                              void* d_out, int out_size) {
    (void)n_in; (void)out_size;
    const float* X = (const float*)d_in[0];
    const float* M = (const float*)d_in[1];
    if (in_sizes[0] == S_ROWS * D_DIM) {
        X = (const float*)d_in[1];
        M = (const float*)d_in[0];
    }
    float* out = (float*)d_out;

    cudaFuncSetAttribute(gemm_kernel,
                         cudaFuncAttributeMaxDynamicSharedMemorySize, SMEM_BYTES);

    convert_all_kernel<<<B_ROWS + S_ROWS, 256>>>(X, M);

    dim3 grid(S_ROWS / BN, B_ROWS / BM);  // (16, 64) = 1024 CTAs
    gemm_kernel<<<grid, NTHREADS, SMEM_BYTES>>>(out);
}

// round 10
// speedup vs baseline: 1.5797x; 1.5797x over previous
#include <cuda_runtime.h>
#include <cuda_fp16.h>
#include <cstdint>
#include <cstddef>

// ---------------------------------------------------------------------------
// Problem constants
// ---------------------------------------------------------------------------
static constexpr int D_DIM  = 2496;   // 16*13*12
static constexpr int B_ROWS = 4096;
static constexpr int S_ROWS = 2048;

// Centered formulation: x~ = x - 0.5, m~ = m - 0.5 (sq_dist shift-invariant).
// out = -0.002*|x~|^2 - 0.002*|m~|^2 + 0.004*(x~.m~)
static constexpr float K_CROSS = 0.004f;
static constexpr float K_SQ    = -0.002f;

// GEMM tiling: quarter tiles, fp16 f16-accumulate mma (R8 config — at the
// legacy-mma dispatch wall, ~3% over floor; do not touch).
static constexpr int BM = 64;
static constexpr int BN = 128;
static constexpr int BK = 32;
static constexpr int KITERS = D_DIM / BK; // 78 exact
static constexpr int STAGES = 4;
static constexpr int NTHREADS = 256;      // 8 warps: 2(M) x 4(N), warp tile 32x32

// Padded smem rows: 64 B data + 16 B pad = 80 B stride (conflict-free).
static constexpr int ROW_STRIDE  = 80;
static constexpr int A_ST_BYTES  = BM * ROW_STRIDE;           // 5120
static constexpr int B_ST_BYTES  = BN * ROW_STRIDE;           // 10240
static constexpr int STAGE_BYTES = A_ST_BYTES + B_ST_BYTES;   // 15360
static constexpr int OFF_STATS   = STAGES * STAGE_BYTES;      // 61440
static constexpr int SMEM_BYTES  = OFF_STATS + (BM + BN) * 4; // 62208

// ---------------------------------------------------------------------------
// Device scratch
// ---------------------------------------------------------------------------
__device__ __align__(128) __half g_Xh[(size_t)B_ROWS * D_DIM];
__device__ __align__(128) __half g_Mh[(size_t)S_ROWS * D_DIM];
__device__ float g_ax[B_ROWS];   // -0.002 * |x~|^2
__device__ float g_bx[S_ROWS];   // -0.002 * |m~|^2

// ---------------------------------------------------------------------------
// Helpers
// ---------------------------------------------------------------------------
__device__ __forceinline__ uint32_t smem_u32(const void* p) {
    uint32_t a;
    asm("{ .reg .u64 t; cvta.to.shared.u64 t, %1; cvt.u32.u64 %0, t; }"
        : "=r"(a) : "l"(p));
    return a;
}

__device__ __forceinline__ void cp_async16(uint32_t dst, const void* src) {
    asm volatile("cp.async.cg.shared.global [%0], [%1], 16;" :: "r"(dst), "l"(src));
}

__device__ __forceinline__ void ldmat_x4(uint32_t* r, uint32_t addr) {
    asm volatile("ldmatrix.sync.aligned.m8n8.x4.shared.b16 {%0,%1,%2,%3}, [%4];"
                 : "=r"(r[0]), "=r"(r[1]), "=r"(r[2]), "=r"(r[3]) : "r"(addr));
}

__device__ __forceinline__ void mma_f16acc(uint32_t* c, const uint32_t* a,
                                           const uint32_t* b) {
    asm volatile(
        "mma.sync.aligned.m16n8k16.row.col.f16.f16.f16.f16 "
        "{%0,%1}, {%2,%3,%4,%5}, {%6,%7}, {%0,%1};"
        : "+r"(c[0]), "+r"(c[1])
        : "r"(a[0]), "r"(a[1]), "r"(a[2]), "r"(a[3]), "r"(b[0]), "r"(b[1]));
}

// ---------------------------------------------------------------------------
// Stage loader: A tile 64x32 fp16, B tile 128x32 fp16 via cp.async (16B)
// ---------------------------------------------------------------------------
__device__ __forceinline__ void load_stage(uint32_t sbase,
                                           const __half* __restrict__ Xt,
                                           const __half* __restrict__ Mt,
                                           int tid) {
    {
        int row = tid >> 2, ch = tid & 3;
        cp_async16(sbase + row * ROW_STRIDE + ch * 16,
                   Xt + (size_t)row * D_DIM + ch * 8);
    }
#pragma unroll
    for (int i = 0; i < 2; i++) {
        int idx = i * NTHREADS + tid;
        int row = idx >> 2, ch = idx & 3;
        cp_async16(sbase + A_ST_BYTES + row * ROW_STRIDE + ch * 16,
                   Mt + (size_t)row * D_DIM + ch * 8);
    }
}

// ---------------------------------------------------------------------------
// Convert: one WARP per row. fp32 -> centered fp16 + prescaled row sumsq.
// 19.5 float4 per lane (deep MLP), shfl-only reduction, no barriers.
// ---------------------------------------------------------------------------
static constexpr int ROW_F4 = D_DIM / 4;        // 624 float4 per row
static constexpr int ROWS_PER_BLK = 8;          // 8 warps per 256-thr block

__global__ void __launch_bounds__(256)
convert_all_kernel(const float* __restrict__ X, const float* __restrict__ M) {
    const int wid  = threadIdx.x >> 5;
    const int lane = threadIdx.x & 31;
    const int b    = blockIdx.x * ROWS_PER_BLK + wid;
    const bool isX = (b < B_ROWS);
    const int row  = isX ? b : b - B_ROWS;
    const float4* src = (const float4*)((isX ? X : M) + (size_t)row * D_DIM);
    uint2* dst = (uint2*)((isX ? g_Xh : g_Mh) + (size_t)row * D_DIM);
    float* coef = isX ? &g_ax[row] : &g_bx[row];

    float acc = 0.f;
#pragma unroll 5
    for (int i = lane; i < ROW_F4; i += 32) {
        float4 v = src[i];
        float c0 = v.x - 0.5f, c1 = v.y - 0.5f;
        float c2 = v.z - 0.5f, c3 = v.w - 0.5f;
        acc = fmaf(c0, c0, acc);
        acc = fmaf(c1, c1, acc);
        acc = fmaf(c2, c2, acc);
        acc = fmaf(c3, c3, acc);
        __half2 lo = __floats2half2_rn(c0, c1);
        __half2 hi = __floats2half2_rn(c2, c3);
        uint2 o;
        o.x = *(uint32_t*)&lo;
        o.y = *(uint32_t*)&hi;
        dst[i] = o;
    }
#pragma unroll
    for (int o = 16; o > 0; o >>= 1) acc += __shfl_xor_sync(0xffffffffu, acc, o);
    if (lane == 0) *coef = acc * K_SQ;
}

// ---------------------------------------------------------------------------
// GEMM + fused epilogue: out[b,s] = ax[b] + bx[s] + 0.004 * cross
// 256 threads = 8 warps in 2(M) x 4(N); warp tile 32x32. 2 CTAs/SM.
// ---------------------------------------------------------------------------
__global__ void __launch_bounds__(NTHREADS, 2)
gemm_kernel(float* __restrict__ out) {
    extern __shared__ char smem[];
    const uint32_t smem_base = smem_u32(smem);
    const int tid    = threadIdx.x;
    const int wid    = tid >> 5;
    const int lane   = tid & 31;
    const int warp_m = wid >> 2;          // 0..1
    const int warp_n = wid & 3;           // 0..3
    const int bn     = blockIdx.x;        // 0..15
    const int bm     = blockIdx.y;        // 0..63

    float* xs_s = (float*)(smem + OFF_STATS);
    float* ms_s = xs_s + BM;
    if (tid < BM) xs_s[tid] = g_ax[bm * BM + tid];
    if (tid < BN) ms_s[tid] = g_bx[bn * BN + tid];

    const __half* Xbase = g_Xh + (size_t)(bm * BM) * D_DIM;
    const __half* Mbase = g_Mh + (size_t)(bn * BN) * D_DIM;

#pragma unroll
    for (int s = 0; s < STAGES - 1; s++) {
        load_stage(smem_base + s * STAGE_BYTES,
                   Xbase + (size_t)s * BK, Mbase + (size_t)s * BK, tid);
        asm volatile("cp.async.commit_group;" ::: "memory");
    }

    uint32_t acc[2][4][2];
#pragma unroll
    for (int t = 0; t < 2; t++)
#pragma unroll
        for (int u = 0; u < 4; u++) { acc[t][u][0] = 0u; acc[t][u][1] = 0u; }

    const int a_row = warp_m * 32 + (lane & 15);
    const int a_sel = (lane >> 4) * 16;
    const int b_grp = lane >> 3;
    const int b_row = warp_n * 32 + ((b_grp >> 1) * 8) + (lane & 7);
    const int b_sel = (b_grp & 1) * 16;

#pragma unroll 1
    for (int kk = 0; kk < KITERS; kk++) {
        asm volatile("cp.async.wait_group 2;" ::: "memory");
        __syncthreads();

        int kn = kk + STAGES - 1;
        if (kn < KITERS) {
            load_stage(smem_base + (kn & 3) * STAGE_BYTES,
                       Xbase + (size_t)kn * BK, Mbase + (size_t)kn * BK, tid);
        }
        asm volatile("cp.async.commit_group;" ::: "memory");

        const uint32_t sA = smem_base + (kk & 3) * STAGE_BYTES;
        const uint32_t sB = sA + A_ST_BYTES;

#pragma unroll
        for (int ks = 0; ks < 2; ks++) {              // two k16 steps per BK=32
            const int koff = ks * 32;                 // bytes
            uint32_t a[2][4], b[4][2];
#pragma unroll
            for (int t = 0; t < 2; t++)
                ldmat_x4(a[t], sA + (a_row + t * 16) * ROW_STRIDE + koff + a_sel);
#pragma unroll
            for (int v = 0; v < 2; v++) {             // 2 x4 loads -> 4 n8 frags
                uint32_t r[4];
                ldmat_x4(r, sB + (b_row + v * 16) * ROW_STRIDE + koff + b_sel);
                b[v * 2 + 0][0] = r[0]; b[v * 2 + 0][1] = r[1];
                b[v * 2 + 1][0] = r[2]; b[v * 2 + 1][1] = r[3];
            }
#pragma unroll
            for (int t = 0; t < 2; t++)
#pragma unroll
                for (int u = 0; u < 4; u++)
                    mma_f16acc(acc[t][u], a[t], b[u]);
        }
    }

    // ---------------- Epilogue ----------------
    const int g  = lane >> 2;
    const int tg = lane & 3;

#pragma unroll
    for (int t = 0; t < 2; t++) {
        const int r0 = warp_m * 32 + t * 16 + g;
        const float axa = xs_s[r0];
        const float axb = xs_s[r0 + 8];
        float* o0 = out + (size_t)(bm * BM + r0) * S_ROWS + bn * BN;
        float* o1 = o0 + (size_t)8 * S_ROWS;
#pragma unroll
        for (int u = 0; u < 4; u++) {
            const int col = warp_n * 32 + u * 8 + tg * 2;
            const float m0 = ms_s[col], m1 = ms_s[col + 1];
            float2 clo = __half22float2(*(__half2*)&acc[t][u][0]);  // row r0
            float2 chi = __half22float2(*(__half2*)&acc[t][u][1]);  // row r0+8
            float2 v0, v1;
            v0.x = axa + m0 + K_CROSS * clo.x;
            v0.y = axa + m1 + K_CROSS * clo.y;
            v1.x = axb + m0 + K_CROSS * chi.x;
            v1.y = axb + m1 + K_CROSS * chi.y;
            *(float2*)(o0 + col) = v0;
            *(float2*)(o1 + col) = v1;
        }
    }
}

// ---------------------------------------------------------------------------
// Launch
// ---------------------------------------------------------------------------
extern "C" void kernel_launch(void* const* d_in, const int* in_sizes, int n_in,
                              void* d_out, int out_size) {
    (void)n_in; (void)out_size;
    const float* X = (const float*)d_in[0];   // observation        [4096, 2496]
    const float* M = (const float*)d_in[1];   // observation_matrix [2048, 2496]
    if (in_sizes[0] == S_ROWS * D_DIM) {      // robust to ordering
        X = (const float*)d_in[1];
        M = (const float*)d_in[0];
    }
    float* out = (float*)d_out;

    cudaFuncSetAttribute(gemm_kernel,
                         cudaFuncAttributeMaxDynamicSharedMemorySize, SMEM_BYTES);

    convert_all_kernel<<<(B_ROWS + S_ROWS) / ROWS_PER_BLK, 256>>>(X, M);

    dim3 grid(S_ROWS / BN, B_ROWS / BM);  // (16, 64) = 1024 CTAs
    gemm_kernel<<<grid, NTHREADS, SMEM_BYTES>>>(out);
}

// round 11
// speedup vs baseline: 1.6214x; 1.0264x over previous
#include <cuda_runtime.h>
#include <cuda_fp16.h>
#include <cstdint>
#include <cstddef>

// ---------------------------------------------------------------------------
// Problem constants
// ---------------------------------------------------------------------------
static constexpr int D_DIM  = 2496;   // 16*13*12
static constexpr int B_ROWS = 4096;
static constexpr int S_ROWS = 2048;

// Centered formulation: x~ = x - 0.5, m~ = m - 0.5 (sq_dist shift-invariant).
// out = -0.002*|x~|^2 - 0.002*|m~|^2 + 0.004*(x~.m~)
static constexpr float K_CROSS = 0.004f;
static constexpr float K_SQ    = -0.002f;

// GEMM tiling: quarter tiles, fp16 f16-acc mma, BK=64 stages (half the
// barriers of BK=32), 3-stage cp.async ring.
static constexpr int BM = 64;
static constexpr int BN = 128;
static constexpr int BK = 64;
static constexpr int KITERS = D_DIM / BK; // 39 exact
static constexpr int STAGES = 3;
static constexpr int NTHREADS = 256;      // 8 warps: 2(M) x 4(N), warp tile 32x32

// Padded smem rows: 128 B data + 16 B pad = 144 B stride.
// 144 B = 36 words; row r starts at bank 4r mod 32 -> 8 consecutive rows all
// distinct banks: conflict-free for cp.async 16B stores and ldmatrix reads.
static constexpr int ROW_STRIDE  = 144;
static constexpr int A_ST_BYTES  = BM * ROW_STRIDE;           // 9216
static constexpr int B_ST_BYTES  = BN * ROW_STRIDE;           // 18432
static constexpr int STAGE_BYTES = A_ST_BYTES + B_ST_BYTES;   // 27648
static constexpr int OFF_STATS   = STAGES * STAGE_BYTES;      // 82944
static constexpr int SMEM_BYTES  = OFF_STATS + (BM + BN) * 4; // 83712

// ---------------------------------------------------------------------------
// Device scratch
// ---------------------------------------------------------------------------
__device__ __align__(128) __half g_Xh[(size_t)B_ROWS * D_DIM];
__device__ __align__(128) __half g_Mh[(size_t)S_ROWS * D_DIM];
__device__ float g_ax[B_ROWS];   // -0.002 * |x~|^2
__device__ float g_bx[S_ROWS];   // -0.002 * |m~|^2

// ---------------------------------------------------------------------------
// Helpers
// ---------------------------------------------------------------------------
__device__ __forceinline__ uint32_t smem_u32(const void* p) {
    uint32_t a;
    asm("{ .reg .u64 t; cvta.to.shared.u64 t, %1; cvt.u32.u64 %0, t; }"
        : "=r"(a) : "l"(p));
    return a;
}

__device__ __forceinline__ void cp_async16(uint32_t dst, const void* src) {
    asm volatile("cp.async.cg.shared.global [%0], [%1], 16;" :: "r"(dst), "l"(src));
}

__device__ __forceinline__ void ldmat_x4(uint32_t* r, uint32_t addr) {
    asm volatile("ldmatrix.sync.aligned.m8n8.x4.shared.b16 {%0,%1,%2,%3}, [%4];"
                 : "=r"(r[0]), "=r"(r[1]), "=r"(r[2]), "=r"(r[3]) : "r"(addr));
}

__device__ __forceinline__ void mma_f16acc(uint32_t* c, const uint32_t* a,
                                           const uint32_t* b) {
    asm volatile(
        "mma.sync.aligned.m16n8k16.row.col.f16.f16.f16.f16 "
        "{%0,%1}, {%2,%3,%4,%5}, {%6,%7}, {%0,%1};"
        : "+r"(c[0]), "+r"(c[1])
        : "r"(a[0]), "r"(a[1]), "r"(a[2]), "r"(a[3]), "r"(b[0]), "r"(b[1]));
}

// ---------------------------------------------------------------------------
// Stage loader: A tile 64x64 fp16 (8192 B), B tile 128x64 fp16 (16384 B).
// 1536 chunks of 16 B over 256 threads: A 2/thread, B 4/thread.
// ---------------------------------------------------------------------------
__device__ __forceinline__ void load_stage(uint32_t sbase,
                                           const __half* __restrict__ Xt,
                                           const __half* __restrict__ Mt,
                                           int tid) {
#pragma unroll
    for (int i = 0; i < 2; i++) {                 // A: 512 chunks
        int idx = i * NTHREADS + tid;
        int row = idx >> 3, ch = idx & 7;
        cp_async16(sbase + row * ROW_STRIDE + ch * 16,
                   Xt + (size_t)row * D_DIM + ch * 8);
    }
#pragma unroll
    for (int i = 0; i < 4; i++) {                 // B: 1024 chunks
        int idx = i * NTHREADS + tid;
        int row = idx >> 3, ch = idx & 7;
        cp_async16(sbase + A_ST_BYTES + row * ROW_STRIDE + ch * 16,
                   Mt + (size_t)row * D_DIM + ch * 8);
    }
}

// ---------------------------------------------------------------------------
// Convert: one WARP per row. fp32 -> centered fp16 + prescaled row sumsq.
// ---------------------------------------------------------------------------
static constexpr int ROW_F4 = D_DIM / 4;        // 624 float4 per row
static constexpr int ROWS_PER_BLK = 8;

__global__ void __launch_bounds__(256)
convert_all_kernel(const float* __restrict__ X, const float* __restrict__ M) {
    const int wid  = threadIdx.x >> 5;
    const int lane = threadIdx.x & 31;
    const int b    = blockIdx.x * ROWS_PER_BLK + wid;
    const bool isX = (b < B_ROWS);
    const int row  = isX ? b : b - B_ROWS;
    const float4* src = (const float4*)((isX ? X : M) + (size_t)row * D_DIM);
    uint2* dst = (uint2*)((isX ? g_Xh : g_Mh) + (size_t)row * D_DIM);
    float* coef = isX ? &g_ax[row] : &g_bx[row];

    float acc = 0.f;
#pragma unroll 5
    for (int i = lane; i < ROW_F4; i += 32) {
        float4 v = src[i];
        float c0 = v.x - 0.5f, c1 = v.y - 0.5f;
        float c2 = v.z - 0.5f, c3 = v.w - 0.5f;
        acc = fmaf(c0, c0, acc);
        acc = fmaf(c1, c1, acc);
        acc = fmaf(c2, c2, acc);
        acc = fmaf(c3, c3, acc);
        __half2 lo = __floats2half2_rn(c0, c1);
        __half2 hi = __floats2half2_rn(c2, c3);
        uint2 o;
        o.x = *(uint32_t*)&lo;
        o.y = *(uint32_t*)&hi;
        dst[i] = o;
    }
#pragma unroll
    for (int o = 16; o > 0; o >>= 1) acc += __shfl_xor_sync(0xffffffffu, acc, o);
    if (lane == 0) *coef = acc * K_SQ;
}

// ---------------------------------------------------------------------------
// GEMM + fused epilogue: out[b,s] = ax[b] + bx[s] + 0.004 * cross
// 256 threads = 8 warps in 2(M) x 4(N); warp tile 32x32. 2 CTAs/SM.
// ---------------------------------------------------------------------------
__global__ void __launch_bounds__(NTHREADS, 2)
gemm_kernel(float* __restrict__ out) {
    extern __shared__ char smem[];
    const uint32_t smem_base = smem_u32(smem);
    const int tid    = threadIdx.x;
    const int wid    = tid >> 5;
    const int lane   = tid & 31;
    const int warp_m = wid >> 2;          // 0..1
    const int warp_n = wid & 3;           // 0..3
    const int bn     = blockIdx.x;        // 0..15
    const int bm     = blockIdx.y;        // 0..63

    float* xs_s = (float*)(smem + OFF_STATS);
    float* ms_s = xs_s + BM;
    if (tid < BM) xs_s[tid] = g_ax[bm * BM + tid];
    if (tid < BN) ms_s[tid] = g_bx[bn * BN + tid];

    const __half* Xbase = g_Xh + (size_t)(bm * BM) * D_DIM;
    const __half* Mbase = g_Mh + (size_t)(bn * BN) * D_DIM;

    // Prologue: fill stages 0,1
#pragma unroll
    for (int s = 0; s < STAGES - 1; s++) {
        load_stage(smem_base + s * STAGE_BYTES,
                   Xbase + (size_t)s * BK, Mbase + (size_t)s * BK, tid);
        asm volatile("cp.async.commit_group;" ::: "memory");
    }

    uint32_t acc[2][4][2];
#pragma unroll
    for (int t = 0; t < 2; t++)
#pragma unroll
        for (int u = 0; u < 4; u++) { acc[t][u][0] = 0u; acc[t][u][1] = 0u; }

    const int a_row = warp_m * 32 + (lane & 15);
    const int a_sel = (lane >> 4) * 16;
    const int b_grp = lane >> 3;
    const int b_row = warp_n * 32 + ((b_grp >> 1) * 8) + (lane & 7);
    const int b_sel = (b_grp & 1) * 16;

    int slot_cur = 0;   // stage slot for iteration kk
    int slot_pre = 2;   // stage slot for iteration kk+2

#pragma unroll 1
    for (int kk = 0; kk < KITERS; kk++) {
        asm volatile("cp.async.wait_group 1;" ::: "memory");
        __syncthreads();

        int kn = kk + STAGES - 1;
        if (kn < KITERS) {
            load_stage(smem_base + slot_pre * STAGE_BYTES,
                       Xbase + (size_t)kn * BK, Mbase + (size_t)kn * BK, tid);
        }
        asm volatile("cp.async.commit_group;" ::: "memory");

        const uint32_t sA = smem_base + slot_cur * STAGE_BYTES;
        const uint32_t sB = sA + A_ST_BYTES;
        slot_cur = (slot_cur == 2) ? 0 : slot_cur + 1;
        slot_pre = (slot_pre == 2) ? 0 : slot_pre + 1;

#pragma unroll
        for (int ks = 0; ks < 4; ks++) {              // four k16 steps per BK=64
            const int koff = ks * 32;                 // bytes
            uint32_t a[2][4], b[4][2];
#pragma unroll
            for (int t = 0; t < 2; t++)
                ldmat_x4(a[t], sA + (a_row + t * 16) * ROW_STRIDE + koff + a_sel);
#pragma unroll
            for (int v = 0; v < 2; v++) {             // 2 x4 loads -> 4 n8 frags
                uint32_t r[4];
                ldmat_x4(r, sB + (b_row + v * 16) * ROW_STRIDE + koff + b_sel);
                b[v * 2 + 0][0] = r[0]; b[v * 2 + 0][1] = r[1];
                b[v * 2 + 1][0] = r[2]; b[v * 2 + 1][1] = r[3];
            }
#pragma unroll
            for (int t = 0; t < 2; t++)
#pragma unroll
                for (int u = 0; u < 4; u++)
                    mma_f16acc(acc[t][u], a[t], b[u]);
        }
    }

    // ---------------- Epilogue ----------------
    const int g  = lane >> 2;
    const int tg = lane & 3;

#pragma unroll
    for (int t = 0; t < 2; t++) {
        const int r0 = warp_m * 32 + t * 16 + g;
        const float axa = xs_s[r0];
        const float axb = xs_s[r0 + 8];
        float* o0 = out + (size_t)(bm * BM + r0) * S_ROWS + bn * BN;
        float* o1 = o0 + (size_t)8 * S_ROWS;
#pragma unroll
        for (int u = 0; u < 4; u++) {
            const int col = warp_n * 32 + u * 8 + tg * 2;
            const float m0 = ms_s[col], m1 = ms_s[col + 1];
            float2 clo = __half22float2(*(__half2*)&acc[t][u][0]);  // row r0
            float2 chi = __half22float2(*(__half2*)&acc[t][u][1]);  // row r0+8
            float2 v0, v1;
            v0.x = axa + m0 + K_CROSS * clo.x;
            v0.y = axa + m1 + K_CROSS * clo.y;
            v1.x = axb + m0 + K_CROSS * chi.x;
            v1.y = axb + m1 + K_CROSS * chi.y;
            *(float2*)(o0 + col) = v0;
            *(float2*)(o1 + col) = v1;
        }
    }
}

// ---------------------------------------------------------------------------
// Launch
// ---------------------------------------------------------------------------
extern "C" void kernel_launch(void* const* d_in, const int* in_sizes, int n_in,
                              void* d_out, int out_size) {
    (void)n_in; (void)out_size;
    const float* X = (const float*)d_in[0];   // observation        [4096, 2496]
    const float* M = (const float*)d_in[1];   // observation_matrix [2048, 2496]
    if (in_sizes[0] == S_ROWS * D_DIM) {      // robust to ordering
        X = (const float*)d_in[1];
        M = (const float*)d_in[0];
    }
    float* out = (float*)d_out;

    cudaFuncSetAttribute(gemm_kernel,
                         cudaFuncAttributeMaxDynamicSharedMemorySize, SMEM_BYTES);

    convert_all_kernel<<<(B_ROWS + S_ROWS) / ROWS_PER_BLK, 256>>>(X, M);

    dim3 grid(S_ROWS / BN, B_ROWS / BM);  // (16, 64) = 1024 CTAs
    gemm_kernel<<<grid, NTHREADS, SMEM_BYTES>>>(out);
}